// round 15
// baseline (speedup 1.0000x reference)
#include <cuda_runtime.h>
#include <cuda_fp16.h>
#include <math.h>
#include <stdint.h>

#define N_ROWS 16384
#define DIM    1024
#define HIDDEN 4096

// ---------------------------------------------------------------------------
// Scratch (static device globals — allocation-free per harness rules)
// All GEMM operands single fp16 plane. Error budget (deterministic inputs):
// measured 4.43e-4 with this precision scheme (R14) — 2.3x under 1e-3.
// s = diag(zA@bil@zB^T) computed as 8 per-column-block partials in GEMM1's
// epilogue (g_sp); t never materialized.
// ---------------------------------------------------------------------------
__device__ __align__(128) __half g_zA  [(size_t)N_ROWS * DIM];
__device__ __align__(128) __half g_bilT[(size_t)DIM * DIM];
__device__ __align__(128) __half g_w1t [(size_t)HIDDEN * HIDDEN];
__device__ __align__(128) __half g_w2t [(size_t)DIM * HIDDEN];
__device__ __align__(128) float  g_sp  [(size_t)N_ROWS * 8];
__device__ __align__(128) __half g_xn  [(size_t)N_ROWS * HIDDEN];
__device__ __align__(128) __half g_h   [(size_t)N_ROWS * HIDDEN];
__device__ __align__(128) float  g_sn  [N_ROWS];

// ---------------------------------------------------------------------------
// Baseline-PTX helpers (sm_80-era features only: cp.async, ldmatrix, mma.sync)
// ---------------------------------------------------------------------------
__device__ __forceinline__ uint32_t smem_u32(const void* p) {
    uint32_t a;
    asm("{ .reg .u64 t; cvta.to.shared.u64 t, %1; cvt.u32.u64 %0, t; }"
        : "=r"(a) : "l"(p));
    return a;
}

#define CP16(dst, src) \
    asm volatile("cp.async.cg.shared.global [%0], [%1], 16;" \
        :: "r"(dst), "l"(src))
#define CP_COMMIT() asm volatile("cp.async.commit_group;" ::: "memory")
#define CP_WAIT0()  asm volatile("cp.async.wait_group 0;" ::: "memory")

#define LDSM_X4(r, addr) \
    asm volatile("ldmatrix.sync.aligned.m8n8.x4.shared.b16 {%0,%1,%2,%3}, [%4];" \
        : "=r"((r)[0]), "=r"((r)[1]), "=r"((r)[2]), "=r"((r)[3]) : "r"(addr))

__device__ __forceinline__ void mma_fp16(float* d, const uint32_t* a,
                                         uint32_t b0, uint32_t b1) {
    asm volatile(
        "mma.sync.aligned.m16n8k16.row.col.f32.f16.f16.f32 "
        "{%0,%1,%2,%3}, {%4,%5,%6,%7}, {%8,%9}, {%0,%1,%2,%3};"
        : "+f"(d[0]), "+f"(d[1]), "+f"(d[2]), "+f"(d[3])
        : "r"(a[0]), "r"(a[1]), "r"(a[2]), "r"(a[3]), "r"(b0), "r"(b1));
}

__device__ __forceinline__ float gelu_exact(float x) {
    return 0.5f * x * (1.0f + erff(x * 0.70710678118654752440f));
}

// ---------------------------------------------------------------------------
// mma.sync GEMM.  D[M,Ncols] = A[M,K] @ B[Ncols,K]^T  (B transposed fp16).
// Converged config (R12-R14 best): BM=BN=128, BK=64 via paired 32-wide
// sub-chunks [A0|B0|A1|B1] per stage (80B-pitch planes), 8 warps (2x4),
// warp tile 64x32, 2-stage cp.async (80KB/CTA, 2 CTAs/SM), ONE __syncthreads
// per 64 K.
// SMEM pitch 80B: bank-group of (row r, chunk c) = (5r + c) mod 8 — complete
// residue system over any 8 consecutive rows -> ldmatrix conflict-free.
// MODE 1: g = gelu(acc + svec[r]*wlast[c] + bias[c]) -> Ch fp16, staged
//         through smem (272B pitch) for fully-coalesced 256B row stores.
// MODE 2: Cf = gelu(acc + bias[c])
// MODE 3: sp_out[r][bx] = sum_c acc[r][c] * zBf[r][c]  (no C store;
//         deterministic shfl + smem reduction)
// ---------------------------------------------------------------------------
#define PLANE_B 10240            // 128 rows * 80B
#define SUB_B   (2 * PLANE_B)    // A,B for one 32-wide sub-chunk
#define STAGE_B (2 * SUB_B)      // two sub-chunks = 64 K per stage (40KB)
#define NSTAGE  2
#define GSM_BYTES (NSTAGE * STAGE_B)   // 81920
#define EPI_PITCH 272            // fp16 staging row pitch: 68 words == 4 mod 32
                                 // -> acc-store banks 4*(lane>>2)+(lane&3) all
                                 // distinct; 272 % 16 == 0 keeps uint4 aligned.

__device__ __forceinline__ void load_stage(
    uint32_t sb, int stage,
    const __half* __restrict__ A, const __half* __restrict__ B,
    int row0, int col0, int k0, int K, int tid)
{
    // Two 32-wide sub-chunks; within each, 1024 16B-chunks: [A:512][B:512].
    #pragma unroll
    for (int sub = 0; sub < 2; sub++) {
        const uint32_t s0 = sb + stage * STAGE_B + sub * SUB_B;
        const int kk = k0 + sub * 32;
        #pragma unroll
        for (int j = 0; j < 4; j++) {
            const int ci    = tid + j * 256;
            const int plane = ci >> 9;          // 0 = A, 1 = B
            const int row   = (ci >> 2) & 127;
            const int ch    = ci & 3;
            const __half* src = (plane == 0 ? A + (size_t)(row0 + row) * K
                                            : B + (size_t)(col0 + row) * K)
                                + kk + ch * 8;
            CP16(s0 + plane * PLANE_B + row * 80 + (ch << 4), src);
        }
    }
    CP_COMMIT();
}

template <int MODE>
__global__ __launch_bounds__(256, 2)
void gemm_mma(const __half* __restrict__ A, const __half* __restrict__ B,
              int K, int Ncols,
              float* __restrict__ Cf, __half* __restrict__ Ch,
              const float* __restrict__ bias, const float* __restrict__ wlast,
              const float* __restrict__ svec,
              const float* __restrict__ zBf, float* __restrict__ sp_out)
{
    extern __shared__ __align__(128) char smem[];
    __shared__ float spart[4][128];   // MODE 3 cross-warp reduction (2KB)
    const uint32_t sb = smem_u32(smem);
    const int tid  = threadIdx.x;
    const int lane = tid & 31;
    const int warp = tid >> 5;
    const int wm   = warp & 1;     // 0..1 -> 64-row panel
    const int wn   = warp >> 1;    // 0..3 -> 32-col panel
    const int row0 = blockIdx.y * 128;
    const int col0 = blockIdx.x * 128;

    const int nch = K >> 6;        // 64 K per iteration

    load_stage(sb, 0, A, B, row0, col0, 0, K, tid);

    float acc[4][4][4];
    #pragma unroll
    for (int a = 0; a < 4; a++)
        #pragma unroll
        for (int b = 0; b < 4; b++)
            #pragma unroll
            for (int c = 0; c < 4; c++) acc[a][b][c] = 0.0f;

    // ldmatrix lane geometry
    const int arow = wm * 64 + (lane & 7) + ((lane >> 3) & 1) * 8;  // M row
    const int ak   = lane >> 4;                                      // k half
    const int brow = wn * 32 + (lane & 7) + ((lane >> 4) & 1) * 8;  // N row
    const int bk   = (lane >> 3) & 1;

    for (int i = 0; i < nch; i++) {
        CP_WAIT0();            // own shard of stage i arrived
        __syncthreads();       // all shards visible; all warps done with stage i-1
        if (i + 1 < nch)       // refill other buffer; overlap with MMA of stage i
            load_stage(sb, (i + 1) & 1, A, B,
                       row0, col0, (i + 1) << 6, K, tid);

        const uint32_t st = sb + (i & 1) * STAGE_B;
        #pragma unroll
        for (int sub = 0; sub < 2; sub++) {
            const uint32_t ss = st + sub * SUB_B;
            #pragma unroll
            for (int ks = 0; ks < 2; ks++) {
                uint32_t ahf[4][4];
                #pragma unroll
                for (int mi = 0; mi < 4; mi++) {
                    const uint32_t ra = ss + (arow + mi * 16) * 80 +
                                        ((ks * 2 + ak) << 4);
                    LDSM_X4(ahf[mi], ra);
                }
                #pragma unroll
                for (int np = 0; np < 2; np++) {
                    const uint32_t rb = ss + PLANE_B + (brow + np * 16) * 80 +
                                        ((ks * 2 + bk) << 4);
                    uint32_t bhf[4];
                    LDSM_X4(bhf, rb);
                    #pragma unroll
                    for (int mi = 0; mi < 4; mi++) {
                        mma_fp16(acc[mi][np * 2 + 0], ahf[mi], bhf[0], bhf[1]);
                        mma_fp16(acc[mi][np * 2 + 1], ahf[mi], bhf[2], bhf[3]);
                    }
                }
            }
        }
    }

    // Epilogue. acc layout per mma: c0,c1 -> (r, c..c+1); c2,c3 -> (r+8, c..c+1)
    const int r_base = row0 + wm * 64 + (lane >> 2);
    const int c_base = col0 + wn * 32 + (lane & 3) * 2;

    if (MODE == 3) {
        // Partial row-dot with zB over this CTA's 128-column block.
        float part[4][2];
        #pragma unroll
        for (int mi = 0; mi < 4; mi++) { part[mi][0] = 0.0f; part[mi][1] = 0.0f; }
        #pragma unroll
        for (int mi = 0; mi < 4; mi++) {
            const int r = r_base + mi * 16;
            #pragma unroll
            for (int ni = 0; ni < 4; ni++) {
                const int c = c_base + ni * 8;
                const float2 z0 = *reinterpret_cast<const float2*>(
                    zBf + (size_t)r * Ncols + c);
                const float2 z1 = *reinterpret_cast<const float2*>(
                    zBf + (size_t)(r + 8) * Ncols + c);
                part[mi][0] += acc[mi][ni][0] * z0.x + acc[mi][ni][1] * z0.y;
                part[mi][1] += acc[mi][ni][2] * z1.x + acc[mi][ni][3] * z1.y;
            }
        }
        // Reduce over the 4 lanes sharing the same rows (lane & 3 group).
        #pragma unroll
        for (int off = 1; off < 4; off <<= 1)
            #pragma unroll
            for (int mi = 0; mi < 4; mi++) {
                part[mi][0] += __shfl_xor_sync(0xFFFFFFFFu, part[mi][0], off);
                part[mi][1] += __shfl_xor_sync(0xFFFFFFFFu, part[mi][1], off);
            }
        __syncthreads();   // main loop fully done before reusing barrier
        if ((lane & 3) == 0) {
            #pragma unroll
            for (int mi = 0; mi < 4; mi++) {
                const int rl = wm * 64 + (lane >> 2) + mi * 16;
                spart[wn][rl]     = part[mi][0];
                spart[wn][rl + 8] = part[mi][1];
            }
        }
        __syncthreads();
        if (tid < 128) {
            const float s = spart[0][tid] + spart[1][tid] +
                            spart[2][tid] + spart[3][tid];
            sp_out[(size_t)(row0 + tid) * 8 + blockIdx.x] = s;
        }
        return;
    }

    if (MODE == 1) {
        // Hoist ni-only operands (c depends on ni, not mi).
        float bb[4][2], wl[4][2];
        #pragma unroll
        for (int ni = 0; ni < 4; ni++) {
            const int c = c_base + ni * 8;
            bb[ni][0] = __ldg(bias + c);  bb[ni][1] = __ldg(bias + c + 1);
            wl[ni][0] = __ldg(wlast + c); wl[ni][1] = __ldg(wlast + c + 1);
        }
        __syncthreads();   // all warps past final LDSM before smem reuse
        // Stage the 128x128 fp16 tile in smem (272B pitch, conflict-free).
        #pragma unroll
        for (int mi = 0; mi < 4; mi++) {
            const int r  = r_base + mi * 16;
            const int rl = r - row0;                 // local row
            const int cl = (c_base - col0) * 2;      // local col byte offset
            const float sv0 = __ldg(svec + r);
            const float sv1 = __ldg(svec + r + 8);
            #pragma unroll
            for (int ni = 0; ni < 4; ni++) {
                union { __half e[2]; uint32_t u; } H0, H1;
                H0.e[0] = __float2half_rn(gelu_exact(acc[mi][ni][0] + sv0 * wl[ni][0] + bb[ni][0]));
                H0.e[1] = __float2half_rn(gelu_exact(acc[mi][ni][1] + sv0 * wl[ni][1] + bb[ni][1]));
                H1.e[0] = __float2half_rn(gelu_exact(acc[mi][ni][2] + sv1 * wl[ni][0] + bb[ni][0]));
                H1.e[1] = __float2half_rn(gelu_exact(acc[mi][ni][3] + sv1 * wl[ni][1] + bb[ni][1]));
                const uint32_t off = rl * EPI_PITCH + cl + ni * 16;
                *reinterpret_cast<uint32_t*>(smem + off)                 = H0.u;
                *reinterpret_cast<uint32_t*>(smem + off + 8 * EPI_PITCH) = H1.u;
            }
        }
        __syncthreads();
        // Coalesced write-out: 128 rows x 256B, uint4 per thread, 8 sweeps.
        #pragma unroll
        for (int j = 0; j < 8; j++) {
            const int ci  = tid + j * 256;
            const int row = ci >> 4;         // 16 x 16B chunks per row
            const int ch  = ci & 15;
            const uint4 v = *reinterpret_cast<const uint4*>(
                smem + row * EPI_PITCH + ch * 16);
            *reinterpret_cast<uint4*>(
                Ch + (size_t)(row0 + row) * Ncols + col0 + ch * 8) = v;
        }
        return;
    }

    // MODE 2: fp32 out + bias + GELU (float2 quads already cover full sectors)
    #pragma unroll
    for (int mi = 0; mi < 4; mi++) {
        const int r = r_base + mi * 16;
        #pragma unroll
        for (int ni = 0; ni < 4; ni++) {
            const int c = c_base + ni * 8;
            const float bb0 = __ldg(bias + c), bb1 = __ldg(bias + c + 1);
            *reinterpret_cast<float2*>(Cf + (size_t)r * Ncols + c) =
                make_float2(gelu_exact(acc[mi][ni][0] + bb0),
                            gelu_exact(acc[mi][ni][1] + bb1));
            *reinterpret_cast<float2*>(Cf + (size_t)(r + 8) * Ncols + c) =
                make_float2(gelu_exact(acc[mi][ni][2] + bb0),
                            gelu_exact(acc[mi][ni][3] + bb1));
        }
    }
}

// ---------------------------------------------------------------------------
// fp32 -> fp16 convert (elementwise, vectorized)
// ---------------------------------------------------------------------------
__global__ __launch_bounds__(256)
void convert_half_kernel(const float* __restrict__ in, __half* __restrict__ oh,
                         int n4)
{
    const int i = blockIdx.x * 256 + threadIdx.x;
    if (i >= n4) return;
    float4 v = reinterpret_cast<const float4*>(in)[i];
    union { __half e[4]; uint2 u; } H;
    H.e[0] = __float2half_rn(v.x);
    H.e[1] = __float2half_rn(v.y);
    H.e[2] = __float2half_rn(v.z);
    H.e[3] = __float2half_rn(v.w);
    reinterpret_cast<uint2*>(oh)[i] = H.u;
}

// in [R,C] fp32 row-major -> out [C,R] fp16 (transpose)
__global__ __launch_bounds__(256)
void transpose_half_kernel(const float* __restrict__ in, __half* __restrict__ oh,
                           int R, int C)
{
    __shared__ float tile[32][33];
    const int c  = blockIdx.x * 32 + threadIdx.x;
    const int r0 = blockIdx.y * 32;
    #pragma unroll
    for (int i = threadIdx.y; i < 32; i += 8)
        tile[i][threadIdx.x] = in[(size_t)(r0 + i) * C + c];
    __syncthreads();
    const int rr = r0 + threadIdx.x;       // output column (= input row)
    const int cc = blockIdx.x * 32;        // output row base (= input col)
    #pragma unroll
    for (int i = threadIdx.y; i < 32; i += 8)
        oh[(size_t)(cc + i) * R + rr] = __float2half_rn(tile[threadIdx.x][i]);
}

// ---------------------------------------------------------------------------
// Per-row fusion: s = sum of 8 GEMM1 partials; LN over 4097 virtual features;
// emit normalized x (4096 cols) as fp16 + normalized s (fp32).
// zA read as fp16 (zAh — the same plane GEMM1 consumed); zB fp32. Paired
// columns per thread -> __half2/float2 loads, __half2 stores.
// ---------------------------------------------------------------------------
__global__ __launch_bounds__(256)
void row_fuse_kernel(const __half* __restrict__ zAh, const float* __restrict__ zB,
                     const float* __restrict__ spart,
                     const float* __restrict__ ln_g, const float* __restrict__ ln_b,
                     __half* __restrict__ xh, float* __restrict__ sn)
{
    const int n = blockIdx.x;
    const __half* a = zAh + (size_t)n * DIM;
    const float*  b = zB  + (size_t)n * DIM;

    float va[2][2], vb[2][2], vh[2][2], vd[2][2];
    float sp = (threadIdx.x < 8) ? spart[(size_t)n * 8 + threadIdx.x] : 0.0f;
    float sum = 0.0f, sq = 0.0f;

    #pragma unroll
    for (int i = 0; i < 2; i++) {
        const int c = i * 512 + threadIdx.x * 2;
        const __half2 ah = *reinterpret_cast<const __half2*>(a + c);
        const float2  bf = *reinterpret_cast<const float2*>(b + c);
        const float x1[2] = { __half2float(__low2half(ah)),
                              __half2float(__high2half(ah)) };
        const float x2[2] = { bf.x, bf.y };
        #pragma unroll
        for (int j = 0; j < 2; j++) {
            const float hd = x1[j] * x2[j];
            const float df = fabsf(x1[j] - x2[j]);
            va[i][j] = x1[j]; vb[i][j] = x2[j]; vh[i][j] = hd; vd[i][j] = df;
            sum += x1[j] + x2[j] + hd + df;
            sq  = fmaf(x1[j], x1[j], sq); sq = fmaf(x2[j], x2[j], sq);
            sq  = fmaf(hd, hd, sq);       sq = fmaf(df, df, sq);
        }
    }

    #pragma unroll
    for (int off = 16; off > 0; off >>= 1) {
        sp  += __shfl_down_sync(0xFFFFFFFFu, sp,  off);
        sum += __shfl_down_sync(0xFFFFFFFFu, sum, off);
        sq  += __shfl_down_sync(0xFFFFFFFFu, sq,  off);
    }
    __shared__ float red[3][8];
    __shared__ float bc[3];
    const int lane = threadIdx.x & 31;
    const int w    = threadIdx.x >> 5;
    if (lane == 0) { red[0][w] = sp; red[1][w] = sum; red[2][w] = sq; }
    __syncthreads();
    if (threadIdx.x == 0) {
        float S = 0, SU = 0, SQ = 0;
        #pragma unroll
        for (int i = 0; i < 8; i++) { S += red[0][i]; SU += red[1][i]; SQ += red[2][i]; }
        bc[0] = S; bc[1] = SU; bc[2] = SQ;
    }
    __syncthreads();

    const float s     = bc[0];
    const float total = bc[1] + s;
    const float totsq = bc[2] + s * s;
    const float inv   = 1.0f / 4097.0f;
    const float mean  = total * inv;
    const float var   = totsq * inv - mean * mean;
    const float rstd  = rsqrtf(var + 1e-5f);

    __half* xhr = xh + (size_t)n * HIDDEN;
    #pragma unroll
    for (int i = 0; i < 2; i++) {
        const int c = i * 512 + threadIdx.x * 2;
        #pragma unroll
        for (int seg = 0; seg < 4; seg++) {
            const int cc = seg * 1024 + c;
            const float g0 = ln_g[cc], g1 = ln_g[cc + 1];
            const float o0 = ln_b[cc], o1 = ln_b[cc + 1];
            float s0, s1;
            if (seg == 0)      { s0 = va[i][0]; s1 = va[i][1]; }
            else if (seg == 1) { s0 = vb[i][0]; s1 = vb[i][1]; }
            else if (seg == 2) { s0 = vh[i][0]; s1 = vh[i][1]; }
            else               { s0 = vd[i][0]; s1 = vd[i][1]; }
            const float v0 = (s0 - mean) * rstd * g0 + o0;
            const float v1 = (s1 - mean) * rstd * g1 + o1;
            *reinterpret_cast<__half2*>(xhr + cc) =
                __floats2half2_rn(v0, v1);
        }
    }
    if (threadIdx.x == 0)
        sn[n] = (s - mean) * rstd * ln_g[4096] + ln_b[4096];
}

// ---------------------------------------------------------------------------
extern "C" void kernel_launch(void* const* d_in, const int* in_sizes, int n_in,
                              void* d_out, int out_size)
{
    const float* zA   = (const float*)d_in[0];
    const float* zB   = (const float*)d_in[1];
    const float* bil  = (const float*)d_in[2];
    const float* ln_g = (const float*)d_in[3];
    const float* ln_b = (const float*)d_in[4];
    const float* W1   = (const float*)d_in[5];
    const float* b1   = (const float*)d_in[6];
    const float* W2   = (const float*)d_in[7];
    const float* b2   = (const float*)d_in[8];
    float* out = (float*)d_out;

    __half *zAh, *bilT, *w1t, *w2t, *xn, *h;
    float *sp, *sn;
    cudaGetSymbolAddress((void**)&zAh,  g_zA);
    cudaGetSymbolAddress((void**)&bilT, g_bilT);
    cudaGetSymbolAddress((void**)&w1t,  g_w1t);
    cudaGetSymbolAddress((void**)&w2t,  g_w2t);
    cudaGetSymbolAddress((void**)&sp,   g_sp);
    cudaGetSymbolAddress((void**)&xn,   g_xn);
    cudaGetSymbolAddress((void**)&h,    g_h);
    cudaGetSymbolAddress((void**)&sn,   g_sn);

    cudaFuncSetAttribute(gemm_mma<3>, cudaFuncAttributeMaxDynamicSharedMemorySize, GSM_BYTES);
    cudaFuncSetAttribute(gemm_mma<1>, cudaFuncAttributeMaxDynamicSharedMemorySize, GSM_BYTES);
    cudaFuncSetAttribute(gemm_mma<2>, cudaFuncAttributeMaxDynamicSharedMemorySize, GSM_BYTES);

    // 0) operand conversions
    convert_half_kernel<<<(N_ROWS * DIM / 4 + 255) / 256, 256>>>(zA, zAh, N_ROWS * DIM / 4);
    transpose_half_kernel<<<dim3(DIM / 32, DIM / 32), dim3(32, 8)>>>(bil, bilT, DIM, DIM);
    transpose_half_kernel<<<dim3(HIDDEN / 32, HIDDEN / 32), dim3(32, 8)>>>(W1, w1t, HIDDEN, HIDDEN);
    transpose_half_kernel<<<dim3(DIM / 32, HIDDEN / 32), dim3(32, 8)>>>(W2, w2t, HIDDEN, DIM);

    // 1) s partials: per CTA column-block, sp[n][bx] = sum_c (zA@bil)[n,c]*zB[n,c]
    gemm_mma<3><<<dim3(DIM / 128, N_ROWS / 128), 256, GSM_BYTES>>>(
        zAh, bilT, DIM, DIM, nullptr, nullptr,
        nullptr, nullptr, nullptr, zB, sp);

    // 2) s + LayerNorm -> xn (fp16), sn
    row_fuse_kernel<<<N_ROWS, 256>>>(zAh, zB, sp, ln_g, ln_b, xn, sn);

    // 3) h = gelu(xn @ W1[:4096] + sn*W1[4096,:] + b1)  (fp16 out, staged)
    gemm_mma<1><<<dim3(HIDDEN / 128, N_ROWS / 128), 256, GSM_BYTES>>>(
        xn, w1t, HIDDEN, HIDDEN, nullptr, h,
        b1, W1 + (size_t)4096 * HIDDEN, sn, nullptr, nullptr);

    // 4) out = gelu(h @ W2 + b2)  (fp32)
    gemm_mma<2><<<dim3(DIM / 128, N_ROWS / 128), 256, GSM_BYTES>>>(
        h, w2t, HIDDEN, DIM, out, nullptr,
        b2, nullptr, nullptr, nullptr, nullptr);
}

// round 16
// speedup vs baseline: 1.0165x; 1.0165x over previous
#include <cuda_runtime.h>
#include <cuda_fp16.h>
#include <math.h>
#include <stdint.h>

#define N_ROWS 16384
#define DIM    1024
#define HIDDEN 4096

// ---------------------------------------------------------------------------
// FINAL KERNEL (R14 configuration — best measured: 2138.6 us, rel_err 4.43e-4)
// Scratch (static device globals — allocation-free per harness rules)
// All GEMM operands single fp16 plane. Error budget (deterministic inputs):
// 2.3x under the 1e-3 threshold.
// s = diag(zA@bil@zB^T) computed as 8 per-column-block partials in GEMM1's
// epilogue (g_sp); t never materialized.
// ---------------------------------------------------------------------------
__device__ __align__(128) __half g_zA  [(size_t)N_ROWS * DIM];
__device__ __align__(128) __half g_bilT[(size_t)DIM * DIM];
__device__ __align__(128) __half g_w1t [(size_t)HIDDEN * HIDDEN];
__device__ __align__(128) __half g_w2t [(size_t)DIM * HIDDEN];
__device__ __align__(128) float  g_sp  [(size_t)N_ROWS * 8];
__device__ __align__(128) __half g_xn  [(size_t)N_ROWS * HIDDEN];
__device__ __align__(128) __half g_h   [(size_t)N_ROWS * HIDDEN];
__device__ __align__(128) float  g_sn  [N_ROWS];

// ---------------------------------------------------------------------------
// Baseline-PTX helpers (sm_80-era features only: cp.async, ldmatrix, mma.sync)
// ---------------------------------------------------------------------------
__device__ __forceinline__ uint32_t smem_u32(const void* p) {
    uint32_t a;
    asm("{ .reg .u64 t; cvta.to.shared.u64 t, %1; cvt.u32.u64 %0, t; }"
        : "=r"(a) : "l"(p));
    return a;
}

#define CP16(dst, src) \
    asm volatile("cp.async.cg.shared.global [%0], [%1], 16;" \
        :: "r"(dst), "l"(src))
#define CP_COMMIT() asm volatile("cp.async.commit_group;" ::: "memory")
#define CP_WAIT0()  asm volatile("cp.async.wait_group 0;" ::: "memory")

#define LDSM_X4(r, addr) \
    asm volatile("ldmatrix.sync.aligned.m8n8.x4.shared.b16 {%0,%1,%2,%3}, [%4];" \
        : "=r"((r)[0]), "=r"((r)[1]), "=r"((r)[2]), "=r"((r)[3]) : "r"(addr))

__device__ __forceinline__ void mma_fp16(float* d, const uint32_t* a,
                                         uint32_t b0, uint32_t b1) {
    asm volatile(
        "mma.sync.aligned.m16n8k16.row.col.f32.f16.f16.f32 "
        "{%0,%1,%2,%3}, {%4,%5,%6,%7}, {%8,%9}, {%0,%1,%2,%3};"
        : "+f"(d[0]), "+f"(d[1]), "+f"(d[2]), "+f"(d[3])
        : "r"(a[0]), "r"(a[1]), "r"(a[2]), "r"(a[3]), "r"(b0), "r"(b1));
}

__device__ __forceinline__ float gelu_exact(float x) {
    return 0.5f * x * (1.0f + erff(x * 0.70710678118654752440f));
}

// ---------------------------------------------------------------------------
// mma.sync GEMM.  D[M,Ncols] = A[M,K] @ B[Ncols,K]^T  (B transposed fp16).
// Converged config: BM=BN=128, BK=64 via paired 32-wide sub-chunks
// [A0|B0|A1|B1] per stage (80B-pitch planes), 8 warps (2x4), warp tile
// 64x32, 2-stage cp.async (80KB/CTA, 2 CTAs/SM), ONE __syncthreads per 64 K.
// SMEM pitch 80B: bank-group of (row r, chunk c) = (5r + c) mod 8 — complete
// residue system over any 8 consecutive rows -> ldmatrix conflict-free.
// MODE 1: g = gelu(acc + svec[r]*wlast[c] + bias[c]) -> Ch fp16
// MODE 2: Cf = gelu(acc + bias[c])
// MODE 3: sp_out[r][bx] = sum_c acc[r][c] * zBf[r][c]  (no C store;
//         deterministic shfl + smem reduction)
// ---------------------------------------------------------------------------
#define PLANE_B 10240            // 128 rows * 80B
#define SUB_B   (2 * PLANE_B)    // A,B for one 32-wide sub-chunk
#define STAGE_B (2 * SUB_B)      // two sub-chunks = 64 K per stage (40KB)
#define NSTAGE  2
#define GSM_BYTES (NSTAGE * STAGE_B)   // 81920

__device__ __forceinline__ void load_stage(
    uint32_t sb, int stage,
    const __half* __restrict__ A, const __half* __restrict__ B,
    int row0, int col0, int k0, int K, int tid)
{
    // Two 32-wide sub-chunks; within each, 1024 16B-chunks: [A:512][B:512].
    #pragma unroll
    for (int sub = 0; sub < 2; sub++) {
        const uint32_t s0 = sb + stage * STAGE_B + sub * SUB_B;
        const int kk = k0 + sub * 32;
        #pragma unroll
        for (int j = 0; j < 4; j++) {
            const int ci    = tid + j * 256;
            const int plane = ci >> 9;          // 0 = A, 1 = B
            const int row   = (ci >> 2) & 127;
            const int ch    = ci & 3;
            const __half* src = (plane == 0 ? A + (size_t)(row0 + row) * K
                                            : B + (size_t)(col0 + row) * K)
                                + kk + ch * 8;
            CP16(s0 + plane * PLANE_B + row * 80 + (ch << 4), src);
        }
    }
    CP_COMMIT();
}

template <int MODE>
__global__ __launch_bounds__(256, 2)
void gemm_mma(const __half* __restrict__ A, const __half* __restrict__ B,
              int K, int Ncols,
              float* __restrict__ Cf, __half* __restrict__ Ch,
              const float* __restrict__ bias, const float* __restrict__ wlast,
              const float* __restrict__ svec,
              const float* __restrict__ zBf, float* __restrict__ sp_out)
{
    extern __shared__ __align__(128) char smem[];
    __shared__ float spart[4][128];   // MODE 3 cross-warp reduction (2KB)
    const uint32_t sb = smem_u32(smem);
    const int tid  = threadIdx.x;
    const int lane = tid & 31;
    const int warp = tid >> 5;
    const int wm   = warp & 1;     // 0..1 -> 64-row panel
    const int wn   = warp >> 1;    // 0..3 -> 32-col panel
    const int row0 = blockIdx.y * 128;
    const int col0 = blockIdx.x * 128;

    const int nch = K >> 6;        // 64 K per iteration

    load_stage(sb, 0, A, B, row0, col0, 0, K, tid);

    float acc[4][4][4];
    #pragma unroll
    for (int a = 0; a < 4; a++)
        #pragma unroll
        for (int b = 0; b < 4; b++)
            #pragma unroll
            for (int c = 0; c < 4; c++) acc[a][b][c] = 0.0f;

    // ldmatrix lane geometry
    const int arow = wm * 64 + (lane & 7) + ((lane >> 3) & 1) * 8;  // M row
    const int ak   = lane >> 4;                                      // k half
    const int brow = wn * 32 + (lane & 7) + ((lane >> 4) & 1) * 8;  // N row
    const int bk   = (lane >> 3) & 1;

    for (int i = 0; i < nch; i++) {
        CP_WAIT0();            // own shard of stage i arrived
        __syncthreads();       // all shards visible; all warps done with stage i-1
        if (i + 1 < nch)       // refill other buffer; overlap with MMA of stage i
            load_stage(sb, (i + 1) & 1, A, B,
                       row0, col0, (i + 1) << 6, K, tid);

        const uint32_t st = sb + (i & 1) * STAGE_B;
        #pragma unroll
        for (int sub = 0; sub < 2; sub++) {
            const uint32_t ss = st + sub * SUB_B;
            #pragma unroll
            for (int ks = 0; ks < 2; ks++) {
                uint32_t ahf[4][4];
                #pragma unroll
                for (int mi = 0; mi < 4; mi++) {
                    const uint32_t ra = ss + (arow + mi * 16) * 80 +
                                        ((ks * 2 + ak) << 4);
                    LDSM_X4(ahf[mi], ra);
                }
                #pragma unroll
                for (int np = 0; np < 2; np++) {
                    const uint32_t rb = ss + PLANE_B + (brow + np * 16) * 80 +
                                        ((ks * 2 + bk) << 4);
                    uint32_t bhf[4];
                    LDSM_X4(bhf, rb);
                    #pragma unroll
                    for (int mi = 0; mi < 4; mi++) {
                        mma_fp16(acc[mi][np * 2 + 0], ahf[mi], bhf[0], bhf[1]);
                        mma_fp16(acc[mi][np * 2 + 1], ahf[mi], bhf[2], bhf[3]);
                    }
                }
            }
        }
    }

    // Epilogue. acc layout per mma: c0,c1 -> (r, c..c+1); c2,c3 -> (r+8, c..c+1)
    const int r_base = row0 + wm * 64 + (lane >> 2);
    const int c_base = col0 + wn * 32 + (lane & 3) * 2;

    if (MODE == 3) {
        // Partial row-dot with zB over this CTA's 128-column block.
        float part[4][2];
        #pragma unroll
        for (int mi = 0; mi < 4; mi++) { part[mi][0] = 0.0f; part[mi][1] = 0.0f; }
        #pragma unroll
        for (int mi = 0; mi < 4; mi++) {
            const int r = r_base + mi * 16;
            #pragma unroll
            for (int ni = 0; ni < 4; ni++) {
                const int c = c_base + ni * 8;
                const float2 z0 = *reinterpret_cast<const float2*>(
                    zBf + (size_t)r * Ncols + c);
                const float2 z1 = *reinterpret_cast<const float2*>(
                    zBf + (size_t)(r + 8) * Ncols + c);
                part[mi][0] += acc[mi][ni][0] * z0.x + acc[mi][ni][1] * z0.y;
                part[mi][1] += acc[mi][ni][2] * z1.x + acc[mi][ni][3] * z1.y;
            }
        }
        // Reduce over the 4 lanes sharing the same rows (lane & 3 group).
        #pragma unroll
        for (int off = 1; off < 4; off <<= 1)
            #pragma unroll
            for (int mi = 0; mi < 4; mi++) {
                part[mi][0] += __shfl_xor_sync(0xFFFFFFFFu, part[mi][0], off);
                part[mi][1] += __shfl_xor_sync(0xFFFFFFFFu, part[mi][1], off);
            }
        __syncthreads();   // main loop fully done before reusing barrier
        if ((lane & 3) == 0) {
            #pragma unroll
            for (int mi = 0; mi < 4; mi++) {
                const int rl = wm * 64 + (lane >> 2) + mi * 16;
                spart[wn][rl]     = part[mi][0];
                spart[wn][rl + 8] = part[mi][1];
            }
        }
        __syncthreads();
        if (tid < 128) {
            const float s = spart[0][tid] + spart[1][tid] +
                            spart[2][tid] + spart[3][tid];
            sp_out[(size_t)(row0 + tid) * 8 + blockIdx.x] = s;
        }
        return;
    }

    #pragma unroll
    for (int mi = 0; mi < 4; mi++) {
        const int r = r_base + mi * 16;
        float sv0 = 0.0f, sv1 = 0.0f;
        if (MODE == 1) { sv0 = __ldg(svec + r); sv1 = __ldg(svec + r + 8); }
        #pragma unroll
        for (int ni = 0; ni < 4; ni++) {
            const int c = c_base + ni * 8;
            float v0 = acc[mi][ni][0], v1 = acc[mi][ni][1];
            float v2 = acc[mi][ni][2], v3 = acc[mi][ni][3];
            if (MODE == 2) {
                const float bb0 = __ldg(bias + c), bb1 = __ldg(bias + c + 1);
                *reinterpret_cast<float2*>(Cf + (size_t)r * Ncols + c) =
                    make_float2(gelu_exact(v0 + bb0), gelu_exact(v1 + bb1));
                *reinterpret_cast<float2*>(Cf + (size_t)(r + 8) * Ncols + c) =
                    make_float2(gelu_exact(v2 + bb0), gelu_exact(v3 + bb1));
            } else {
                const float bb0 = __ldg(bias + c), bb1 = __ldg(bias + c + 1);
                const float wl0 = __ldg(wlast + c), wl1 = __ldg(wlast + c + 1);
                union { __half e[2]; uint32_t u; } H0, H1;
                H0.e[0] = __float2half_rn(gelu_exact(v0 + sv0 * wl0 + bb0));
                H0.e[1] = __float2half_rn(gelu_exact(v1 + sv0 * wl1 + bb1));
                H1.e[0] = __float2half_rn(gelu_exact(v2 + sv1 * wl0 + bb0));
                H1.e[1] = __float2half_rn(gelu_exact(v3 + sv1 * wl1 + bb1));
                *reinterpret_cast<uint32_t*>(Ch + (size_t)r * Ncols + c)       = H0.u;
                *reinterpret_cast<uint32_t*>(Ch + (size_t)(r + 8) * Ncols + c) = H1.u;
            }
        }
    }
}

// ---------------------------------------------------------------------------
// fp32 -> fp16 convert (elementwise, vectorized)
// ---------------------------------------------------------------------------
__global__ __launch_bounds__(256)
void convert_half_kernel(const float* __restrict__ in, __half* __restrict__ oh,
                         int n4)
{
    const int i = blockIdx.x * 256 + threadIdx.x;
    if (i >= n4) return;
    float4 v = reinterpret_cast<const float4*>(in)[i];
    union { __half e[4]; uint2 u; } H;
    H.e[0] = __float2half_rn(v.x);
    H.e[1] = __float2half_rn(v.y);
    H.e[2] = __float2half_rn(v.z);
    H.e[3] = __float2half_rn(v.w);
    reinterpret_cast<uint2*>(oh)[i] = H.u;
}

// in [R,C] fp32 row-major -> out [C,R] fp16 (transpose)
__global__ __launch_bounds__(256)
void transpose_half_kernel(const float* __restrict__ in, __half* __restrict__ oh,
                           int R, int C)
{
    __shared__ float tile[32][33];
    const int c  = blockIdx.x * 32 + threadIdx.x;
    const int r0 = blockIdx.y * 32;
    #pragma unroll
    for (int i = threadIdx.y; i < 32; i += 8)
        tile[i][threadIdx.x] = in[(size_t)(r0 + i) * C + c];
    __syncthreads();
    const int rr = r0 + threadIdx.x;       // output column (= input row)
    const int cc = blockIdx.x * 32;        // output row base (= input col)
    #pragma unroll
    for (int i = threadIdx.y; i < 32; i += 8)
        oh[(size_t)(cc + i) * R + rr] = __float2half_rn(tile[threadIdx.x][i]);
}

// ---------------------------------------------------------------------------
// Per-row fusion: s = sum of 8 GEMM1 partials; LN over 4097 virtual features;
// emit normalized x (4096 cols) as fp16 + normalized s (fp32).
// zA read as fp16 (zAh — the same plane GEMM1 consumed); zB fp32. Paired
// columns per thread -> __half2/float2 loads, __half2 stores.
// ---------------------------------------------------------------------------
__global__ __launch_bounds__(256)
void row_fuse_kernel(const __half* __restrict__ zAh, const float* __restrict__ zB,
                     const float* __restrict__ spart,
                     const float* __restrict__ ln_g, const float* __restrict__ ln_b,
                     __half* __restrict__ xh, float* __restrict__ sn)
{
    const int n = blockIdx.x;
    const __half* a = zAh + (size_t)n * DIM;
    const float*  b = zB  + (size_t)n * DIM;

    float va[2][2], vb[2][2], vh[2][2], vd[2][2];
    float sp = (threadIdx.x < 8) ? spart[(size_t)n * 8 + threadIdx.x] : 0.0f;
    float sum = 0.0f, sq = 0.0f;

    #pragma unroll
    for (int i = 0; i < 2; i++) {
        const int c = i * 512 + threadIdx.x * 2;
        const __half2 ah = *reinterpret_cast<const __half2*>(a + c);
        const float2  bf = *reinterpret_cast<const float2*>(b + c);
        const float x1[2] = { __half2float(__low2half(ah)),
                              __half2float(__high2half(ah)) };
        const float x2[2] = { bf.x, bf.y };
        #pragma unroll
        for (int j = 0; j < 2; j++) {
            const float hd = x1[j] * x2[j];
            const float df = fabsf(x1[j] - x2[j]);
            va[i][j] = x1[j]; vb[i][j] = x2[j]; vh[i][j] = hd; vd[i][j] = df;
            sum += x1[j] + x2[j] + hd + df;
            sq  = fmaf(x1[j], x1[j], sq); sq = fmaf(x2[j], x2[j], sq);
            sq  = fmaf(hd, hd, sq);       sq = fmaf(df, df, sq);
        }
    }

    #pragma unroll
    for (int off = 16; off > 0; off >>= 1) {
        sp  += __shfl_down_sync(0xFFFFFFFFu, sp,  off);
        sum += __shfl_down_sync(0xFFFFFFFFu, sum, off);
        sq  += __shfl_down_sync(0xFFFFFFFFu, sq,  off);
    }
    __shared__ float red[3][8];
    __shared__ float bc[3];
    const int lane = threadIdx.x & 31;
    const int w    = threadIdx.x >> 5;
    if (lane == 0) { red[0][w] = sp; red[1][w] = sum; red[2][w] = sq; }
    __syncthreads();
    if (threadIdx.x == 0) {
        float S = 0, SU = 0, SQ = 0;
        #pragma unroll
        for (int i = 0; i < 8; i++) { S += red[0][i]; SU += red[1][i]; SQ += red[2][i]; }
        bc[0] = S; bc[1] = SU; bc[2] = SQ;
    }
    __syncthreads();

    const float s     = bc[0];
    const float total = bc[1] + s;
    const float totsq = bc[2] + s * s;
    const float inv   = 1.0f / 4097.0f;
    const float mean  = total * inv;
    const float var   = totsq * inv - mean * mean;
    const float rstd  = rsqrtf(var + 1e-5f);

    __half* xhr = xh + (size_t)n * HIDDEN;
    #pragma unroll
    for (int i = 0; i < 2; i++) {
        const int c = i * 512 + threadIdx.x * 2;
        #pragma unroll
        for (int seg = 0; seg < 4; seg++) {
            const int cc = seg * 1024 + c;
            const float g0 = ln_g[cc], g1 = ln_g[cc + 1];
            const float o0 = ln_b[cc], o1 = ln_b[cc + 1];
            float s0, s1;
            if (seg == 0)      { s0 = va[i][0]; s1 = va[i][1]; }
            else if (seg == 1) { s0 = vb[i][0]; s1 = vb[i][1]; }
            else if (seg == 2) { s0 = vh[i][0]; s1 = vh[i][1]; }
            else               { s0 = vd[i][0]; s1 = vd[i][1]; }
            const float v0 = (s0 - mean) * rstd * g0 + o0;
            const float v1 = (s1 - mean) * rstd * g1 + o1;
            *reinterpret_cast<__half2*>(xhr + cc) =
                __floats2half2_rn(v0, v1);
        }
    }
    if (threadIdx.x == 0)
        sn[n] = (s - mean) * rstd * ln_g[4096] + ln_b[4096];
}

// ---------------------------------------------------------------------------
extern "C" void kernel_launch(void* const* d_in, const int* in_sizes, int n_in,
                              void* d_out, int out_size)
{
    const float* zA   = (const float*)d_in[0];
    const float* zB   = (const float*)d_in[1];
    const float* bil  = (const float*)d_in[2];
    const float* ln_g = (const float*)d_in[3];
    const float* ln_b = (const float*)d_in[4];
    const float* W1   = (const float*)d_in[5];
    const float* b1   = (const float*)d_in[6];
    const float* W2   = (const float*)d_in[7];
    const float* b2   = (const float*)d_in[8];
    float* out = (float*)d_out;

    __half *zAh, *bilT, *w1t, *w2t, *xn, *h;
    float *sp, *sn;
    cudaGetSymbolAddress((void**)&zAh,  g_zA);
    cudaGetSymbolAddress((void**)&bilT, g_bilT);
    cudaGetSymbolAddress((void**)&w1t,  g_w1t);
    cudaGetSymbolAddress((void**)&w2t,  g_w2t);
    cudaGetSymbolAddress((void**)&sp,   g_sp);
    cudaGetSymbolAddress((void**)&xn,   g_xn);
    cudaGetSymbolAddress((void**)&h,    g_h);
    cudaGetSymbolAddress((void**)&sn,   g_sn);

    cudaFuncSetAttribute(gemm_mma<3>, cudaFuncAttributeMaxDynamicSharedMemorySize, GSM_BYTES);
    cudaFuncSetAttribute(gemm_mma<1>, cudaFuncAttributeMaxDynamicSharedMemorySize, GSM_BYTES);
    cudaFuncSetAttribute(gemm_mma<2>, cudaFuncAttributeMaxDynamicSharedMemorySize, GSM_BYTES);

    // 0) operand conversions
    convert_half_kernel<<<(N_ROWS * DIM / 4 + 255) / 256, 256>>>(zA, zAh, N_ROWS * DIM / 4);
    transpose_half_kernel<<<dim3(DIM / 32, DIM / 32), dim3(32, 8)>>>(bil, bilT, DIM, DIM);
    transpose_half_kernel<<<dim3(HIDDEN / 32, HIDDEN / 32), dim3(32, 8)>>>(W1, w1t, HIDDEN, HIDDEN);
    transpose_half_kernel<<<dim3(DIM / 32, HIDDEN / 32), dim3(32, 8)>>>(W2, w2t, HIDDEN, DIM);

    // 1) s partials: per CTA column-block, sp[n][bx] = sum_c (zA@bil)[n,c]*zB[n,c]
    gemm_mma<3><<<dim3(DIM / 128, N_ROWS / 128), 256, GSM_BYTES>>>(
        zAh, bilT, DIM, DIM, nullptr, nullptr,
        nullptr, nullptr, nullptr, zB, sp);

    // 2) s + LayerNorm -> xn (fp16), sn
    row_fuse_kernel<<<N_ROWS, 256>>>(zAh, zB, sp, ln_g, ln_b, xn, sn);

    // 3) h = gelu(xn @ W1[:4096] + sn*W1[4096,:] + b1)  (fp16 out)
    gemm_mma<1><<<dim3(HIDDEN / 128, N_ROWS / 128), 256, GSM_BYTES>>>(
        xn, w1t, HIDDEN, HIDDEN, nullptr, h,
        b1, W1 + (size_t)4096 * HIDDEN, sn, nullptr, nullptr);

    // 4) out = gelu(h @ W2 + b2)  (fp32)
    gemm_mma<2><<<dim3(DIM / 128, N_ROWS / 128), 256, GSM_BYTES>>>(
        h, w2t, HIDDEN, DIM, out, nullptr,
        b2, nullptr, nullptr, nullptr, nullptr);
}

// round 17
// speedup vs baseline: 1.0295x; 1.0129x over previous
#include <cuda_runtime.h>
#include <cuda_fp16.h>
#include <math.h>
#include <stdint.h>

#define N_ROWS 16384
#define DIM    1024
#define HIDDEN 4096

// ---------------------------------------------------------------------------
// R14 GEMM architecture (best measured, reproduced twice) + R17 memory-kernel
// polish: MLP-4 convert, 32x64 float2 transpose, epilogue operand hoist.
// All GEMM operands single fp16 plane; rel_err 4.43e-4 (2.3x under 1e-3).
// s = diag(zA@bil@zB^T) computed as 8 per-column-block partials in GEMM1's
// epilogue (g_sp); t never materialized.
// ---------------------------------------------------------------------------
__device__ __align__(128) __half g_zA  [(size_t)N_ROWS * DIM];
__device__ __align__(128) __half g_bilT[(size_t)DIM * DIM];
__device__ __align__(128) __half g_w1t [(size_t)HIDDEN * HIDDEN];
__device__ __align__(128) __half g_w2t [(size_t)DIM * HIDDEN];
__device__ __align__(128) float  g_sp  [(size_t)N_ROWS * 8];
__device__ __align__(128) __half g_xn  [(size_t)N_ROWS * HIDDEN];
__device__ __align__(128) __half g_h   [(size_t)N_ROWS * HIDDEN];
__device__ __align__(128) float  g_sn  [N_ROWS];

// ---------------------------------------------------------------------------
// Baseline-PTX helpers (sm_80-era features only: cp.async, ldmatrix, mma.sync)
// ---------------------------------------------------------------------------
__device__ __forceinline__ uint32_t smem_u32(const void* p) {
    uint32_t a;
    asm("{ .reg .u64 t; cvta.to.shared.u64 t, %1; cvt.u32.u64 %0, t; }"
        : "=r"(a) : "l"(p));
    return a;
}

#define CP16(dst, src) \
    asm volatile("cp.async.cg.shared.global [%0], [%1], 16;" \
        :: "r"(dst), "l"(src))
#define CP_COMMIT() asm volatile("cp.async.commit_group;" ::: "memory")
#define CP_WAIT0()  asm volatile("cp.async.wait_group 0;" ::: "memory")

#define LDSM_X4(r, addr) \
    asm volatile("ldmatrix.sync.aligned.m8n8.x4.shared.b16 {%0,%1,%2,%3}, [%4];" \
        : "=r"((r)[0]), "=r"((r)[1]), "=r"((r)[2]), "=r"((r)[3]) : "r"(addr))

__device__ __forceinline__ void mma_fp16(float* d, const uint32_t* a,
                                         uint32_t b0, uint32_t b1) {
    asm volatile(
        "mma.sync.aligned.m16n8k16.row.col.f32.f16.f16.f32 "
        "{%0,%1,%2,%3}, {%4,%5,%6,%7}, {%8,%9}, {%0,%1,%2,%3};"
        : "+f"(d[0]), "+f"(d[1]), "+f"(d[2]), "+f"(d[3])
        : "r"(a[0]), "r"(a[1]), "r"(a[2]), "r"(a[3]), "r"(b0), "r"(b1));
}

__device__ __forceinline__ float gelu_exact(float x) {
    return 0.5f * x * (1.0f + erff(x * 0.70710678118654752440f));
}

// ---------------------------------------------------------------------------
// mma.sync GEMM.  D[M,Ncols] = A[M,K] @ B[Ncols,K]^T  (B transposed fp16).
// Converged config: BM=BN=128, BK=64 via paired 32-wide sub-chunks
// [A0|B0|A1|B1] per stage (80B-pitch planes), 8 warps (2x4), warp tile
// 64x32, 2-stage cp.async (80KB/CTA, 2 CTAs/SM), ONE __syncthreads per 64 K.
// SMEM pitch 80B: bank-group of (row r, chunk c) = (5r + c) mod 8 — complete
// residue system over any 8 consecutive rows -> ldmatrix conflict-free.
// MODE 1: g = gelu(acc + svec[r]*wlast[c] + bias[c]) -> Ch fp16
// MODE 2: Cf = gelu(acc + bias[c])
// MODE 3: sp_out[r][bx] = sum_c acc[r][c] * zBf[r][c]  (no C store;
//         deterministic shfl + smem reduction)
// ---------------------------------------------------------------------------
#define PLANE_B 10240            // 128 rows * 80B
#define SUB_B   (2 * PLANE_B)    // A,B for one 32-wide sub-chunk
#define STAGE_B (2 * SUB_B)      // two sub-chunks = 64 K per stage (40KB)
#define NSTAGE  2
#define GSM_BYTES (NSTAGE * STAGE_B)   // 81920

__device__ __forceinline__ void load_stage(
    uint32_t sb, int stage,
    const __half* __restrict__ A, const __half* __restrict__ B,
    int row0, int col0, int k0, int K, int tid)
{
    // Two 32-wide sub-chunks; within each, 1024 16B-chunks: [A:512][B:512].
    #pragma unroll
    for (int sub = 0; sub < 2; sub++) {
        const uint32_t s0 = sb + stage * STAGE_B + sub * SUB_B;
        const int kk = k0 + sub * 32;
        #pragma unroll
        for (int j = 0; j < 4; j++) {
            const int ci    = tid + j * 256;
            const int plane = ci >> 9;          // 0 = A, 1 = B
            const int row   = (ci >> 2) & 127;
            const int ch    = ci & 3;
            const __half* src = (plane == 0 ? A + (size_t)(row0 + row) * K
                                            : B + (size_t)(col0 + row) * K)
                                + kk + ch * 8;
            CP16(s0 + plane * PLANE_B + row * 80 + (ch << 4), src);
        }
    }
    CP_COMMIT();
}

template <int MODE>
__global__ __launch_bounds__(256, 2)
void gemm_mma(const __half* __restrict__ A, const __half* __restrict__ B,
              int K, int Ncols,
              float* __restrict__ Cf, __half* __restrict__ Ch,
              const float* __restrict__ bias, const float* __restrict__ wlast,
              const float* __restrict__ svec,
              const float* __restrict__ zBf, float* __restrict__ sp_out)
{
    extern __shared__ __align__(128) char smem[];
    __shared__ float spart[4][128];   // MODE 3 cross-warp reduction (2KB)
    const uint32_t sb = smem_u32(smem);
    const int tid  = threadIdx.x;
    const int lane = tid & 31;
    const int warp = tid >> 5;
    const int wm   = warp & 1;     // 0..1 -> 64-row panel
    const int wn   = warp >> 1;    // 0..3 -> 32-col panel
    const int row0 = blockIdx.y * 128;
    const int col0 = blockIdx.x * 128;

    const int nch = K >> 6;        // 64 K per iteration

    load_stage(sb, 0, A, B, row0, col0, 0, K, tid);

    float acc[4][4][4];
    #pragma unroll
    for (int a = 0; a < 4; a++)
        #pragma unroll
        for (int b = 0; b < 4; b++)
            #pragma unroll
            for (int c = 0; c < 4; c++) acc[a][b][c] = 0.0f;

    // ldmatrix lane geometry
    const int arow = wm * 64 + (lane & 7) + ((lane >> 3) & 1) * 8;  // M row
    const int ak   = lane >> 4;                                      // k half
    const int brow = wn * 32 + (lane & 7) + ((lane >> 4) & 1) * 8;  // N row
    const int bk   = (lane >> 3) & 1;

    for (int i = 0; i < nch; i++) {
        CP_WAIT0();            // own shard of stage i arrived
        __syncthreads();       // all shards visible; all warps done with stage i-1
        if (i + 1 < nch)       // refill other buffer; overlap with MMA of stage i
            load_stage(sb, (i + 1) & 1, A, B,
                       row0, col0, (i + 1) << 6, K, tid);

        const uint32_t st = sb + (i & 1) * STAGE_B;
        #pragma unroll
        for (int sub = 0; sub < 2; sub++) {
            const uint32_t ss = st + sub * SUB_B;
            #pragma unroll
            for (int ks = 0; ks < 2; ks++) {
                uint32_t ahf[4][4];
                #pragma unroll
                for (int mi = 0; mi < 4; mi++) {
                    const uint32_t ra = ss + (arow + mi * 16) * 80 +
                                        ((ks * 2 + ak) << 4);
                    LDSM_X4(ahf[mi], ra);
                }
                #pragma unroll
                for (int np = 0; np < 2; np++) {
                    const uint32_t rb = ss + PLANE_B + (brow + np * 16) * 80 +
                                        ((ks * 2 + bk) << 4);
                    uint32_t bhf[4];
                    LDSM_X4(bhf, rb);
                    #pragma unroll
                    for (int mi = 0; mi < 4; mi++) {
                        mma_fp16(acc[mi][np * 2 + 0], ahf[mi], bhf[0], bhf[1]);
                        mma_fp16(acc[mi][np * 2 + 1], ahf[mi], bhf[2], bhf[3]);
                    }
                }
            }
        }
    }

    // Epilogue. acc layout per mma: c0,c1 -> (r, c..c+1); c2,c3 -> (r+8, c..c+1)
    const int r_base = row0 + wm * 64 + (lane >> 2);
    const int c_base = col0 + wn * 32 + (lane & 3) * 2;

    if (MODE == 3) {
        // Partial row-dot with zB over this CTA's 128-column block.
        float part[4][2];
        #pragma unroll
        for (int mi = 0; mi < 4; mi++) { part[mi][0] = 0.0f; part[mi][1] = 0.0f; }
        #pragma unroll
        for (int mi = 0; mi < 4; mi++) {
            const int r = r_base + mi * 16;
            #pragma unroll
            for (int ni = 0; ni < 4; ni++) {
                const int c = c_base + ni * 8;
                const float2 z0 = *reinterpret_cast<const float2*>(
                    zBf + (size_t)r * Ncols + c);
                const float2 z1 = *reinterpret_cast<const float2*>(
                    zBf + (size_t)(r + 8) * Ncols + c);
                part[mi][0] += acc[mi][ni][0] * z0.x + acc[mi][ni][1] * z0.y;
                part[mi][1] += acc[mi][ni][2] * z1.x + acc[mi][ni][3] * z1.y;
            }
        }
        // Reduce over the 4 lanes sharing the same rows (lane & 3 group).
        #pragma unroll
        for (int off = 1; off < 4; off <<= 1)
            #pragma unroll
            for (int mi = 0; mi < 4; mi++) {
                part[mi][0] += __shfl_xor_sync(0xFFFFFFFFu, part[mi][0], off);
                part[mi][1] += __shfl_xor_sync(0xFFFFFFFFu, part[mi][1], off);
            }
        __syncthreads();   // main loop fully done before reusing barrier
        if ((lane & 3) == 0) {
            #pragma unroll
            for (int mi = 0; mi < 4; mi++) {
                const int rl = wm * 64 + (lane >> 2) + mi * 16;
                spart[wn][rl]     = part[mi][0];
                spart[wn][rl + 8] = part[mi][1];
            }
        }
        __syncthreads();
        if (tid < 128) {
            const float s = spart[0][tid] + spart[1][tid] +
                            spart[2][tid] + spart[3][tid];
            sp_out[(size_t)(row0 + tid) * 8 + blockIdx.x] = s;
        }
        return;
    }

    // Hoist ni-only operands (c depends on ni, not mi) — value-identical.
    float bb[4][2], wl[4][2];
    #pragma unroll
    for (int ni = 0; ni < 4; ni++) {
        const int c = c_base + ni * 8;
        bb[ni][0] = __ldg(bias + c);
        bb[ni][1] = __ldg(bias + c + 1);
        if (MODE == 1) {
            wl[ni][0] = __ldg(wlast + c);
            wl[ni][1] = __ldg(wlast + c + 1);
        }
    }

    #pragma unroll
    for (int mi = 0; mi < 4; mi++) {
        const int r = r_base + mi * 16;
        float sv0 = 0.0f, sv1 = 0.0f;
        if (MODE == 1) { sv0 = __ldg(svec + r); sv1 = __ldg(svec + r + 8); }
        #pragma unroll
        for (int ni = 0; ni < 4; ni++) {
            const int c = c_base + ni * 8;
            float v0 = acc[mi][ni][0], v1 = acc[mi][ni][1];
            float v2 = acc[mi][ni][2], v3 = acc[mi][ni][3];
            if (MODE == 2) {
                *reinterpret_cast<float2*>(Cf + (size_t)r * Ncols + c) =
                    make_float2(gelu_exact(v0 + bb[ni][0]),
                                gelu_exact(v1 + bb[ni][1]));
                *reinterpret_cast<float2*>(Cf + (size_t)(r + 8) * Ncols + c) =
                    make_float2(gelu_exact(v2 + bb[ni][0]),
                                gelu_exact(v3 + bb[ni][1]));
            } else {
                union { __half e[2]; uint32_t u; } H0, H1;
                H0.e[0] = __float2half_rn(gelu_exact(v0 + sv0 * wl[ni][0] + bb[ni][0]));
                H0.e[1] = __float2half_rn(gelu_exact(v1 + sv0 * wl[ni][1] + bb[ni][1]));
                H1.e[0] = __float2half_rn(gelu_exact(v2 + sv1 * wl[ni][0] + bb[ni][0]));
                H1.e[1] = __float2half_rn(gelu_exact(v3 + sv1 * wl[ni][1] + bb[ni][1]));
                *reinterpret_cast<uint32_t*>(Ch + (size_t)r * Ncols + c)       = H0.u;
                *reinterpret_cast<uint32_t*>(Ch + (size_t)(r + 8) * Ncols + c) = H1.u;
            }
        }
    }
}

// ---------------------------------------------------------------------------
// fp32 -> fp16 convert. 4 float4 per thread (MLP 4) to cover DRAM latency.
// Grid covers n4 exactly (n4 % 1024 == 0 for all callers).
// ---------------------------------------------------------------------------
__global__ __launch_bounds__(256)
void convert_half_kernel(const float* __restrict__ in, __half* __restrict__ oh,
                         int n4)
{
    const int base = blockIdx.x * 1024 + threadIdx.x;
    #pragma unroll
    for (int j = 0; j < 4; j++) {
        const int i = base + j * 256;
        float4 v = reinterpret_cast<const float4*>(in)[i];
        union { __half e[4]; uint2 u; } H;
        H.e[0] = __float2half_rn(v.x);
        H.e[1] = __float2half_rn(v.y);
        H.e[2] = __float2half_rn(v.z);
        H.e[3] = __float2half_rn(v.w);
        reinterpret_cast<uint2*>(oh)[i] = H.u;
    }
}

// in [R,C] fp32 row-major -> out [C,R] fp16 (transpose).
// 32 in-rows x 64 in-cols per block; float2 loads (MLP 4 x 8B),
// smem ts[64][33] (store-phase reads conflict-free), coalesced fp16 writes.
// Requires R % 32 == 0, C % 64 == 0 (true for all callers).
__global__ __launch_bounds__(256)
void transpose_half_kernel(const float* __restrict__ in, __half* __restrict__ oh,
                           int R, int C)
{
    __shared__ float ts[64][33];
    const int tx = threadIdx.x;          // 0..31
    const int ty = threadIdx.y;          // 0..7
    const int c0 = blockIdx.x * 64;
    const int r0 = blockIdx.y * 32;

    #pragma unroll
    for (int i = 0; i < 4; i++) {
        const int row = ty + i * 8;
        const float2 v = *reinterpret_cast<const float2*>(
            in + (size_t)(r0 + row) * C + c0 + tx * 2);
        ts[tx * 2][row]     = v.x;
        ts[tx * 2 + 1][row] = v.y;
    }
    __syncthreads();

    const int tid = ty * 32 + tx;
    #pragma unroll
    for (int j = 0; j < 8; j++) {
        const int idx  = j * 256 + tid;
        const int orow = idx >> 5;       // 0..63 = local in-col
        const int ocol = idx & 31;       // local in-row
        oh[(size_t)(c0 + orow) * R + r0 + ocol] =
            __float2half_rn(ts[orow][ocol]);
    }
}

// ---------------------------------------------------------------------------
// Per-row fusion: s = sum of 8 GEMM1 partials; LN over 4097 virtual features;
// emit normalized x (4096 cols) as fp16 + normalized s (fp32).
// zA read as fp16 (zAh — the same plane GEMM1 consumed); zB fp32. Paired
// columns per thread -> __half2/float2 loads, __half2 stores.
// ---------------------------------------------------------------------------
__global__ __launch_bounds__(256)
void row_fuse_kernel(const __half* __restrict__ zAh, const float* __restrict__ zB,
                     const float* __restrict__ spart,
                     const float* __restrict__ ln_g, const float* __restrict__ ln_b,
                     __half* __restrict__ xh, float* __restrict__ sn)
{
    const int n = blockIdx.x;
    const __half* a = zAh + (size_t)n * DIM;
    const float*  b = zB  + (size_t)n * DIM;

    float va[2][2], vb[2][2], vh[2][2], vd[2][2];
    float sp = (threadIdx.x < 8) ? spart[(size_t)n * 8 + threadIdx.x] : 0.0f;
    float sum = 0.0f, sq = 0.0f;

    #pragma unroll
    for (int i = 0; i < 2; i++) {
        const int c = i * 512 + threadIdx.x * 2;
        const __half2 ah = *reinterpret_cast<const __half2*>(a + c);
        const float2  bf = *reinterpret_cast<const float2*>(b + c);
        const float x1[2] = { __half2float(__low2half(ah)),
                              __half2float(__high2half(ah)) };
        const float x2[2] = { bf.x, bf.y };
        #pragma unroll
        for (int j = 0; j < 2; j++) {
            const float hd = x1[j] * x2[j];
            const float df = fabsf(x1[j] - x2[j]);
            va[i][j] = x1[j]; vb[i][j] = x2[j]; vh[i][j] = hd; vd[i][j] = df;
            sum += x1[j] + x2[j] + hd + df;
            sq  = fmaf(x1[j], x1[j], sq); sq = fmaf(x2[j], x2[j], sq);
            sq  = fmaf(hd, hd, sq);       sq = fmaf(df, df, sq);
        }
    }

    #pragma unroll
    for (int off = 16; off > 0; off >>= 1) {
        sp  += __shfl_down_sync(0xFFFFFFFFu, sp,  off);
        sum += __shfl_down_sync(0xFFFFFFFFu, sum, off);
        sq  += __shfl_down_sync(0xFFFFFFFFu, sq,  off);
    }
    __shared__ float red[3][8];
    __shared__ float bc[3];
    const int lane = threadIdx.x & 31;
    const int w    = threadIdx.x >> 5;
    if (lane == 0) { red[0][w] = sp; red[1][w] = sum; red[2][w] = sq; }
    __syncthreads();
    if (threadIdx.x == 0) {
        float S = 0, SU = 0, SQ = 0;
        #pragma unroll
        for (int i = 0; i < 8; i++) { S += red[0][i]; SU += red[1][i]; SQ += red[2][i]; }
        bc[0] = S; bc[1] = SU; bc[2] = SQ;
    }
    __syncthreads();

    const float s     = bc[0];
    const float total = bc[1] + s;
    const float totsq = bc[2] + s * s;
    const float inv   = 1.0f / 4097.0f;
    const float mean  = total * inv;
    const float var   = totsq * inv - mean * mean;
    const float rstd  = rsqrtf(var + 1e-5f);

    __half* xhr = xh + (size_t)n * HIDDEN;
    #pragma unroll
    for (int i = 0; i < 2; i++) {
        const int c = i * 512 + threadIdx.x * 2;
        #pragma unroll
        for (int seg = 0; seg < 4; seg++) {
            const int cc = seg * 1024 + c;
            const float g0 = ln_g[cc], g1 = ln_g[cc + 1];
            const float o0 = ln_b[cc], o1 = ln_b[cc + 1];
            float s0, s1;
            if (seg == 0)      { s0 = va[i][0]; s1 = va[i][1]; }
            else if (seg == 1) { s0 = vb[i][0]; s1 = vb[i][1]; }
            else if (seg == 2) { s0 = vh[i][0]; s1 = vh[i][1]; }
            else               { s0 = vd[i][0]; s1 = vd[i][1]; }
            const float v0 = (s0 - mean) * rstd * g0 + o0;
            const float v1 = (s1 - mean) * rstd * g1 + o1;
            *reinterpret_cast<__half2*>(xhr + cc) =
                __floats2half2_rn(v0, v1);
        }
    }
    if (threadIdx.x == 0)
        sn[n] = (s - mean) * rstd * ln_g[4096] + ln_b[4096];
}

// ---------------------------------------------------------------------------
extern "C" void kernel_launch(void* const* d_in, const int* in_sizes, int n_in,
                              void* d_out, int out_size)
{
    const float* zA   = (const float*)d_in[0];
    const float* zB   = (const float*)d_in[1];
    const float* bil  = (const float*)d_in[2];
    const float* ln_g = (const float*)d_in[3];
    const float* ln_b = (const float*)d_in[4];
    const float* W1   = (const float*)d_in[5];
    const float* b1   = (const float*)d_in[6];
    const float* W2   = (const float*)d_in[7];
    const float* b2   = (const float*)d_in[8];
    float* out = (float*)d_out;

    __half *zAh, *bilT, *w1t, *w2t, *xn, *h;
    float *sp, *sn;
    cudaGetSymbolAddress((void**)&zAh,  g_zA);
    cudaGetSymbolAddress((void**)&bilT, g_bilT);
    cudaGetSymbolAddress((void**)&w1t,  g_w1t);
    cudaGetSymbolAddress((void**)&w2t,  g_w2t);
    cudaGetSymbolAddress((void**)&sp,   g_sp);
    cudaGetSymbolAddress((void**)&xn,   g_xn);
    cudaGetSymbolAddress((void**)&h,    g_h);
    cudaGetSymbolAddress((void**)&sn,   g_sn);

    cudaFuncSetAttribute(gemm_mma<3>, cudaFuncAttributeMaxDynamicSharedMemorySize, GSM_BYTES);
    cudaFuncSetAttribute(gemm_mma<1>, cudaFuncAttributeMaxDynamicSharedMemorySize, GSM_BYTES);
    cudaFuncSetAttribute(gemm_mma<2>, cudaFuncAttributeMaxDynamicSharedMemorySize, GSM_BYTES);

    // 0) operand conversions (MLP-4 convert; 32x64 float2 transposes)
    convert_half_kernel<<<N_ROWS * DIM / 4096, 256>>>(zA, zAh, N_ROWS * DIM / 4);
    transpose_half_kernel<<<dim3(DIM / 64, DIM / 32), dim3(32, 8)>>>(bil, bilT, DIM, DIM);
    transpose_half_kernel<<<dim3(HIDDEN / 64, HIDDEN / 32), dim3(32, 8)>>>(W1, w1t, HIDDEN, HIDDEN);
    transpose_half_kernel<<<dim3(DIM / 64, HIDDEN / 32), dim3(32, 8)>>>(W2, w2t, HIDDEN, DIM);

    // 1) s partials: per CTA column-block, sp[n][bx] = sum_c (zA@bil)[n,c]*zB[n,c]
    gemm_mma<3><<<dim3(DIM / 128, N_ROWS / 128), 256, GSM_BYTES>>>(
        zAh, bilT, DIM, DIM, nullptr, nullptr,
        nullptr, nullptr, nullptr, zB, sp);

    // 2) s + LayerNorm -> xn (fp16), sn
    row_fuse_kernel<<<N_ROWS, 256>>>(zAh, zB, sp, ln_g, ln_b, xn, sn);

    // 3) h = gelu(xn @ W1[:4096] + sn*W1[4096,:] + b1)  (fp16 out)
    gemm_mma<1><<<dim3(HIDDEN / 128, N_ROWS / 128), 256, GSM_BYTES>>>(
        xn, w1t, HIDDEN, HIDDEN, nullptr, h,
        b1, W1 + (size_t)4096 * HIDDEN, sn, nullptr, nullptr);

    // 4) out = gelu(h @ W2 + b2)  (fp32)
    gemm_mma<2><<<dim3(DIM / 128, N_ROWS / 128), 256, GSM_BYTES>>>(
        h, w2t, HIDDEN, DIM, out, nullptr,
        b2, nullptr, nullptr, nullptr, nullptr);
}